// round 2
// baseline (speedup 1.0000x reference)
#include <cuda_runtime.h>
#include <cuda_bf16.h>
#include <math.h>

// out[i] = z[i] * dot(pos[i], c)   with  c = (w_tp / (2*sqrt(3))) * W1 @ W2 @ (W3 @ ones(3))
// W1: [3,2], W2: [2,2], W3: [2,3]  (row-major)

__device__ float g_c[3];

__global__ void prep_kernel(const float* __restrict__ w_tp,
                            const float* __restrict__ W1,
                            const float* __restrict__ W2,
                            const float* __restrict__ W3) {
    // single thread: fold the whole MLP into a 3-vector
    float t3[2], t2[2];
    #pragma unroll
    for (int m = 0; m < 2; m++)
        t3[m] = W3[m * 3 + 0] + W3[m * 3 + 1] + W3[m * 3 + 2];
    #pragma unroll
    for (int k = 0; k < 2; k++)
        t2[k] = W2[k * 2 + 0] * t3[0] + W2[k * 2 + 1] * t3[1];
    // scale: (1/sqrt(3)) * (1/sqrt(2)) * (1/sqrt(2)) = 1/(2*sqrt(3))
    const float scale = w_tp[0] * 0.28867513459481287f; // 1/(2*sqrt(3))
    #pragma unroll
    for (int j = 0; j < 3; j++)
        g_c[j] = (W1[j * 2 + 0] * t2[0] + W1[j * 2 + 1] * t2[1]) * scale;
}

__global__ void __launch_bounds__(256)
atoms_kernel(const float4* __restrict__ pos4,
             const int4*   __restrict__ z4,
             float4*       __restrict__ out4,
             int n4, int n) {
    const float c0 = g_c[0], c1 = g_c[1], c2 = g_c[2];
    int i = blockIdx.x * blockDim.x + threadIdx.x;
    const int stride = gridDim.x * blockDim.x;
    for (; i < n4; i += stride) {
        // 4 atoms = 12 floats of pos, laid out as 3 float4 (full 128B lines)
        const float4 a = pos4[3 * i + 0];
        const float4 b = pos4[3 * i + 1];
        const float4 d = pos4[3 * i + 2];
        const int4  zz = z4[i];
        float4 o;
        o.x = (a.x * c0 + a.y * c1 + a.z * c2) * (float)zz.x;
        o.y = (a.w * c0 + b.x * c1 + b.y * c2) * (float)zz.y;
        o.z = (b.z * c0 + b.w * c1 + d.x * c2) * (float)zz.z;
        o.w = (d.y * c0 + d.z * c1 + d.w * c2) * (float)zz.w;
        out4[i] = o;
    }
    // tail (n not divisible by 4) — dead for N=2M, kept for generality
    if ((n & 3) && blockIdx.x == 0 && threadIdx.x == 0) {
        const float* pos = (const float*)pos4;
        const int*   z   = (const int*)z4;
        float*       out = (float*)out4;
        for (int j = 4 * n4; j < n; j++) {
            out[j] = (pos[3 * j + 0] * c0 + pos[3 * j + 1] * c1 + pos[3 * j + 2] * c2)
                     * (float)z[j];
        }
    }
}

extern "C" void kernel_launch(void* const* d_in, const int* in_sizes, int n_in,
                              void* d_out, int out_size) {
    const float* pos  = (const float*)d_in[0];   // [N,3] f32
    const int*   z    = (const int*)d_in[1];     // [N]   i32
    const float* w_tp = (const float*)d_in[2];   // []    f32
    const float* W1   = (const float*)d_in[3];   // [3,2] f32
    const float* W2   = (const float*)d_in[4];   // [2,2] f32
    const float* W3   = (const float*)d_in[5];   // [2,3] f32
    float* out = (float*)d_out;

    const int n  = in_sizes[1];   // N atoms (element count of z)
    const int n4 = n >> 2;

    prep_kernel<<<1, 1>>>(w_tp, W1, W2, W3);

    const int threads = 256;
    int blocks = (n4 + threads - 1) / threads;
    if (blocks < 1) blocks = 1;
    atoms_kernel<<<blocks, threads>>>((const float4*)pos, (const int4*)z,
                                      (float4*)out, n4, n);
}